// round 8
// baseline (speedup 1.0000x reference)
#include <cuda_runtime.h>
#include <cuda_bf16.h>
#include <math.h>
#include <stdint.h>

#define BDIM 64
#define SDIM 2048
#define IDIM 512
#define HDIM 512

// ---------------- device scratch (no cudaMalloc allowed) -------------------
__device__ float g_hb[BDIM * HDIM];
__device__ float g_att[BDIM * SDIM];
__device__ float g_cbar[BDIM * IDIM];
__device__ int   g_mask_is_byte;

__device__ __nv_bfloat16 g_ctx_hi[BDIM * SDIM * IDIM];   // bf16(x)
__device__ unsigned char g_ctx_h8[BDIM * SDIM * IDIM];   // e4m3(x)
__device__ unsigned char g_ctx_l8[BDIM * SDIM * IDIM];   // e4m3(256*(x-bf16(x)))
__device__ __nv_bfloat16 g_wc_hi[HDIM * IDIM];
__device__ unsigned char g_wc_h8[HDIM * IDIM];
__device__ unsigned char g_wc_l8[HDIM * IDIM];

#define INV_SCALE (1.0f / 256.0f)
#define SCALE 256.0f

// ---------------- PTX helpers ----------------------------------------------
__device__ __forceinline__ uint32_t smem_u32(const void* p) {
    uint32_t a;
    asm("{ .reg .u64 t; cvta.to.shared.u64 t, %1; cvt.u32.u64 %0, t; }" : "=r"(a) : "l"(p));
    return a;
}
#define CP16(dst, src) asm volatile("cp.async.cg.shared.global [%0], [%1], 16;" :: "r"(dst), "l"(src))
#define CP_COMMIT()    asm volatile("cp.async.commit_group;" ::: "memory")
#define CP_WAIT(n)     asm volatile("cp.async.wait_group %0;" :: "n"(n) : "memory")

#define LDSM4(r, a)                                                           \
    asm volatile("ldmatrix.sync.aligned.m8n8.x4.shared.b16 {%0,%1,%2,%3}, [%4];" \
        : "=r"((r)[0]), "=r"((r)[1]), "=r"((r)[2]), "=r"((r)[3]) : "r"(a))

#define MMA16816(c, a, b0, b1)                                                \
    asm volatile("mma.sync.aligned.m16n8k16.row.col.f32.bf16.bf16.f32 "       \
        "{%0,%1,%2,%3},{%4,%5,%6,%7},{%8,%9},{%0,%1,%2,%3};"                  \
        : "+f"((c)[0]), "+f"((c)[1]), "+f"((c)[2]), "+f"((c)[3])              \
        : "r"((a)[0]), "r"((a)[1]), "r"((a)[2]), "r"((a)[3]), "r"(b0), "r"(b1))

#define MMAFP8(c, a, b0, b1)                                                  \
    asm volatile("mma.sync.aligned.m16n8k32.row.col.f32.e4m3.e4m3.f32 "       \
        "{%0,%1,%2,%3},{%4,%5,%6,%7},{%8,%9},{%0,%1,%2,%3};"                  \
        : "+f"((c)[0]), "+f"((c)[1]), "+f"((c)[2]), "+f"((c)[3])              \
        : "r"((a)[0]), "r"((a)[1]), "r"((a)[2]), "r"((a)[3]), "r"(b0), "r"(b1))

__device__ __forceinline__ uint32_t pack_e4m3x4(float a, float b, float c, float d) {
    uint16_t lo, hi;
    asm("cvt.rn.satfinite.e4m3x2.f32 %0, %1, %2;" : "=h"(lo) : "f"(b), "f"(a));
    asm("cvt.rn.satfinite.e4m3x2.f32 %0, %1, %2;" : "=h"(hi) : "f"(d), "f"(c));
    return (uint32_t)lo | ((uint32_t)hi << 16);
}

// swizzle for 64-byte fp8 rows: sector ^= (r&3) ^ ((r>>2)&1)
#define SWZ8(r) ((uint32_t)((((r) & 3) ^ (((r) >> 2) & 1)) << 4))

// ---------------------------------------------------------------------------
// K0: detect mask storage (int32 vs uint8)
// ---------------------------------------------------------------------------
__global__ void k0_detect(const unsigned char* __restrict__ mraw) {
    __shared__ int found;
    if (threadIdx.x == 0) found = 0;
    __syncthreads();
    int acc = 0;
    for (int i = threadIdx.x; i < 4096; i += 256)
        if ((i & 3) != 0 && mraw[i] != 0) acc = 1;
    if (acc) atomicOr(&found, 1);
    __syncthreads();
    if (threadIdx.x == 0) g_mask_is_byte = found;
}

// ---------------------------------------------------------------------------
// Kc: fp32 -> bf16 hi + e4m3 hi8 + e4m3 lo8 (scaled by 256)
// ---------------------------------------------------------------------------
__global__ void k_conv(const float* __restrict__ src, __nv_bfloat16* __restrict__ hi,
                       unsigned char* __restrict__ h8, unsigned char* __restrict__ l8,
                       int n4) {
    int i = blockIdx.x * blockDim.x + threadIdx.x;
    if (i >= n4) return;
    float4 v = ((const float4*)src)[i];
    __nv_bfloat16 h0 = __float2bfloat16(v.x), h1 = __float2bfloat16(v.y);
    __nv_bfloat16 h2 = __float2bfloat16(v.z), h3 = __float2bfloat16(v.w);
    float l0 = (v.x - __bfloat162float(h0)) * SCALE;
    float l1 = (v.y - __bfloat162float(h1)) * SCALE;
    float l2 = (v.z - __bfloat162float(h2)) * SCALE;
    float l3 = (v.w - __bfloat162float(h3)) * SCALE;
    __nv_bfloat162* hp = (__nv_bfloat162*)hi;
    hp[i * 2 + 0] = __nv_bfloat162(h0, h1);
    hp[i * 2 + 1] = __nv_bfloat162(h2, h3);
    ((uint32_t*)h8)[i] = pack_e4m3x4(v.x, v.y, v.z, v.w);
    ((uint32_t*)l8)[i] = pack_e4m3x4(l0, l1, l2, l3);
}

// ---------------------------------------------------------------------------
// K1: hb = inp@Wl.T + bl + bc ; zero g_cbar and g_att (warp-per-row, coalesced)
// ---------------------------------------------------------------------------
__global__ void __launch_bounds__(256) k1_hb(const float* __restrict__ inp,
                                             const float* __restrict__ Wl,
                                             const float* __restrict__ bl,
                                             const float* __restrict__ bc) {
    __shared__ float sin[IDIM];
    int b  = blockIdx.x >> 2;
    int hq = blockIdx.x & 3;
    int tid = threadIdx.x;
    int wid = tid >> 5, lane = tid & 31;

    sin[tid] = inp[b * IDIM + tid];
    sin[tid + 256] = inp[b * IDIM + tid + 256];
    g_att[b * SDIM + hq * 512 + tid * 2 + 0] = 0.0f;
    g_att[b * SDIM + hq * 512 + tid * 2 + 1] = 0.0f;
    if (tid < 128) g_cbar[b * IDIM + hq * 128 + tid] = 0.0f;
    __syncthreads();

    const float4* s4 = (const float4*)sin;
    #pragma unroll 1
    for (int r = wid; r < 128; r += 8) {
        int h = hq * 128 + r;
        const float4* w4 = (const float4*)(Wl + (size_t)h * IDIM);
        float acc = 0.0f;
        #pragma unroll
        for (int j = 0; j < 4; j++) {
            float4 w = w4[lane + 32 * j];
            float4 s = s4[lane + 32 * j];
            acc += w.x * s.x + w.y * s.y + w.z * s.z + w.w * s.w;
        }
        #pragma unroll
        for (int o = 16; o > 0; o >>= 1) acc += __shfl_xor_sync(0xffffffffu, acc, o);
        if (lane == 0) g_hb[b * HDIM + h] = acc + bl[h] + bc[h];
    }
}

// ---------------------------------------------------------------------------
// K2: bf16 main term + fp8 cross terms GEMM + tanh + V reduction
// CTA tile: 128(s) x 128(h), K=512 in 8 chunks of 64; 3-stage cp.async.
// Stage (64KB): A16 16K | B16 16K | A8h 8K | A8l 8K | B8h 8K | B8l 8K
// ---------------------------------------------------------------------------
#define STAGE_BYTES 65536
#define SMEM_K2 (3 * STAGE_BYTES)
#define ST_A16 0
#define ST_B16 16384u
#define ST_A8H 32768u
#define ST_A8L 40960u
#define ST_B8H 49152u
#define ST_B8L 57344u

__global__ void __launch_bounds__(256, 1) k2_att_mma(const float* __restrict__ Vv) {
    extern __shared__ char smem[];
    __shared__ float sV[128], sHB[128], attred[128];
    uint32_t sb = smem_u32(smem);

    int tid  = threadIdx.x;
    int wid  = tid >> 5;
    int lane = tid & 31;
    int g    = lane >> 2;
    int tg   = lane & 3;
    int warp_m = wid & 1;
    int warp_n = wid >> 1;

    int bx = blockIdx.x;
    int b     = bx >> 6;
    int stile = (bx >> 2) & 15;
    int htile = bx & 3;
    int s0    = stile * 128;
    int hbase = htile * 128;
    int bb    = b * SDIM;

    if (tid < 128) {
        sV[tid]  = Vv[hbase + tid];
        sHB[tid] = g_hb[b * HDIM + hbase + tid];
        attred[tid] = 0.0f;
    }

    // ---- chunk loader
    auto load_chunk = [&](int kc, int st) {
        int k0 = kc * 64;
        uint32_t base = sb + (uint32_t)st * STAGE_BYTES;
        // A16: 128 rows x 128B
        #pragma unroll
        for (int j = 0; j < 4; j++) {
            int idx = j * 256 + tid;
            int r = idx >> 3, c = idx & 7;
            const __nv_bfloat16* src = g_ctx_hi + ((size_t)(bb + s0 + r) * IDIM + k0 + c * 8);
            uint32_t o = (uint32_t)(r * 128 + c * 16);
            CP16(base + ST_A16 + (o ^ (uint32_t)((r & 7) << 4)), src);
        }
        // B16: 128 rows x 128B
        #pragma unroll
        for (int j = 0; j < 4; j++) {
            int idx = j * 256 + tid;
            int r = idx >> 3, c = idx & 7;
            const __nv_bfloat16* src = g_wc_hi + ((size_t)(hbase + r) * IDIM + k0 + c * 8);
            uint32_t o = (uint32_t)(r * 128 + c * 16);
            CP16(base + ST_B16 + (o ^ (uint32_t)((r & 7) << 4)), src);
        }
        // A8h, A8l: 128 rows x 64B each
        #pragma unroll
        for (int j = 0; j < 2; j++) {
            int idx = j * 256 + tid;
            int r = idx >> 2, c = idx & 3;
            uint32_t o = (uint32_t)(r * 64 + c * 16) ^ SWZ8(r);
            const unsigned char* srcH = g_ctx_h8 + ((size_t)(bb + s0 + r) * IDIM + k0 + c * 16);
            const unsigned char* srcL = g_ctx_l8 + ((size_t)(bb + s0 + r) * IDIM + k0 + c * 16);
            CP16(base + ST_A8H + o, srcH);
            CP16(base + ST_A8L + o, srcL);
        }
        // B8h, B8l
        #pragma unroll
        for (int j = 0; j < 2; j++) {
            int idx = j * 256 + tid;
            int r = idx >> 2, c = idx & 3;
            uint32_t o = (uint32_t)(r * 64 + c * 16) ^ SWZ8(r);
            const unsigned char* srcH = g_wc_h8 + ((size_t)(hbase + r) * IDIM + k0 + c * 16);
            const unsigned char* srcL = g_wc_l8 + ((size_t)(hbase + r) * IDIM + k0 + c * 16);
            CP16(base + ST_B8H + o, srcH);
            CP16(base + ST_B8L + o, srcL);
        }
        CP_COMMIT();
    };

    // ---- ldmatrix address components
    int arow  = warp_m * 64 + (lane & 15);
    uint32_t akoff = (uint32_t)(lane & 16);
    uint32_t axor  = (uint32_t)((lane & 7) << 4);                         // bf16 (128B rows)
    uint32_t axor8 = (uint32_t)((((lane & 3) ^ ((lane >> 2) & 1))) << 4); // fp8 (64B rows)
    int brow  = (lane & 7) + ((lane & 16) >> 1);
    uint32_t bkoff = (uint32_t)(((lane >> 3) & 1) * 16);

    uint32_t aoff[4], boff[2], a8off[4], b8off[2];
    #pragma unroll
    for (int t = 0; t < 4; t++) {
        aoff[t]  = (uint32_t)((arow + t * 16) * 128) + akoff;
        a8off[t] = (uint32_t)((arow + t * 16) * 64) + akoff;
    }
    #pragma unroll
    for (int p = 0; p < 2; p++) {
        boff[p]  = (uint32_t)((warp_n * 32 + p * 16 + brow) * 128) + bkoff;
        b8off[p] = (uint32_t)((warp_n * 32 + p * 16 + brow) * 64) + bkoff;
    }

    float acc[4][4][4];   // main (bf16 hi*hi)
    float accX[4][4][4];  // cross (fp8, scaled by 256)
    #pragma unroll
    for (int t = 0; t < 4; t++)
        #pragma unroll
        for (int n = 0; n < 4; n++)
            #pragma unroll
            for (int c = 0; c < 4; c++) { acc[t][n][c] = 0.0f; accX[t][n][c] = 0.0f; }

    load_chunk(0, 0);
    load_chunk(1, 1);

    #pragma unroll 1
    for (int i = 0; i < 8; i++) {
        if (i + 2 < 8) load_chunk(i + 2, (i + 2) % 3);
        if (i + 2 < 8)      { CP_WAIT(2); }
        else if (i + 1 < 8) { CP_WAIT(1); }
        else                { CP_WAIT(0); }
        __syncthreads();

        uint32_t stb = sb + (uint32_t)(i % 3) * STAGE_BYTES;
        uint32_t A16 = stb + ST_A16, B16 = stb + ST_B16;
        uint32_t A8H = stb + ST_A8H, A8L = stb + ST_A8L;
        uint32_t B8H = stb + ST_B8H, B8L = stb + ST_B8L;

        // ---- main: bf16 hi*hi, 4 k16 steps
        #pragma unroll
        for (int q = 0; q < 4; q++) {
            uint32_t qb = (uint32_t)(q * 32);
            uint32_t aH[4][4], bH[2][4];
            #pragma unroll
            for (int t = 0; t < 4; t++) LDSM4(aH[t], A16 + ((aoff[t] + qb) ^ axor));
            #pragma unroll
            for (int p = 0; p < 2; p++) LDSM4(bH[p], B16 + ((boff[p] + qb) ^ axor));
            #pragma unroll
            for (int t = 0; t < 4; t++)
                #pragma unroll
                for (int nt = 0; nt < 4; nt++) {
                    int p  = nt >> 1;
                    int r0 = (nt & 1) * 2;
                    MMA16816(acc[t][nt], aH[t], bH[p][r0], bH[p][r0 + 1]);
                }
        }

        // ---- cross: fp8 (hi*lo + lo*hi), 2 k32 steps
        #pragma unroll
        for (int st = 0; st < 2; st++) {
            uint32_t sb8 = (uint32_t)(st * 32);
            uint32_t a8h[4][4], a8l[4][4], b8h[2][4], b8l[2][4];
            #pragma unroll
            for (int t = 0; t < 4; t++) {
                LDSM4(a8h[t], A8H + ((a8off[t] + sb8) ^ axor8));
                LDSM4(a8l[t], A8L + ((a8off[t] + sb8) ^ axor8));
            }
            #pragma unroll
            for (int p = 0; p < 2; p++) {
                LDSM4(b8h[p], B8H + ((b8off[p] + sb8) ^ axor8));
                LDSM4(b8l[p], B8L + ((b8off[p] + sb8) ^ axor8));
            }
            #pragma unroll
            for (int t = 0; t < 4; t++)
                #pragma unroll
                for (int nt = 0; nt < 4; nt++) {
                    int p  = nt >> 1;
                    int r0 = (nt & 1) * 2;
                    MMAFP8(accX[t][nt], a8h[t], b8l[p][r0], b8l[p][r0 + 1]);
                    MMAFP8(accX[t][nt], a8l[t], b8h[p][r0], b8h[p][r0 + 1]);
                }
        }
        __syncthreads();
    }

    // ---- epilogue: att[s] += sum_h V[h]*tanh(main + cross/256 + hb[h])
    float rowsum[8];
    #pragma unroll
    for (int r = 0; r < 8; r++) rowsum[r] = 0.0f;
    #pragma unroll
    for (int t = 0; t < 4; t++) {
        #pragma unroll
        for (int nt = 0; nt < 4; nt++) {
            int hh = warp_n * 32 + nt * 8 + tg * 2;
            float v0 = sV[hh], v1 = sV[hh + 1];
            float h0 = sHB[hh], h1 = sHB[hh + 1];
            float* c = acc[t][nt];
            float* x = accX[t][nt];
            rowsum[t * 2 + 0] += v0 * tanhf(c[0] + x[0] * INV_SCALE + h0)
                               + v1 * tanhf(c[1] + x[1] * INV_SCALE + h1);
            rowsum[t * 2 + 1] += v0 * tanhf(c[2] + x[2] * INV_SCALE + h0)
                               + v1 * tanhf(c[3] + x[3] * INV_SCALE + h1);
        }
    }
    #pragma unroll
    for (int r = 0; r < 8; r++) {
        float s = rowsum[r];
        s += __shfl_xor_sync(0xffffffffu, s, 1);
        s += __shfl_xor_sync(0xffffffffu, s, 2);
        if (tg == 0) {
            int row = warp_m * 64 + (r >> 1) * 16 + (r & 1) * 8 + g;
            atomicAdd(&attred[row], s);
        }
    }
    __syncthreads();
    if (tid < 128) atomicAdd(&g_att[b * SDIM + s0 + tid], attred[tid]);
}

// ---------------------------------------------------------------------------
// K3: masked softmax over S per batch -> alpha
// ---------------------------------------------------------------------------
__device__ __forceinline__ bool mask_at(const unsigned char* m, int idx, int is_byte) {
    if (is_byte) return m[idx] != 0;
    return ((const int*)m)[idx] != 0;
}

__global__ void k3_softmax(const unsigned char* __restrict__ mraw,
                           float* __restrict__ alpha) {
    __shared__ float red[256];
    int b = blockIdx.x;
    int tid = threadIdx.x;
    int is_byte = g_mask_is_byte;
    const float NEG_INF = __int_as_float(0xff800000);

    float lmax = NEG_INF;
    for (int s = tid; s < SDIM; s += 256)
        if (!mask_at(mraw, b * SDIM + s, is_byte))
            lmax = fmaxf(lmax, g_att[b * SDIM + s]);
    red[tid] = lmax;
    __syncthreads();
    for (int o = 128; o > 0; o >>= 1) {
        if (tid < o) red[tid] = fmaxf(red[tid], red[tid + o]);
        __syncthreads();
    }
    float smax = red[0];
    __syncthreads();

    float lsum = 0.0f;
    for (int s = tid; s < SDIM; s += 256) {
        float e = 0.0f;
        if (!mask_at(mraw, b * SDIM + s, is_byte))
            e = expf(g_att[b * SDIM + s] - smax);
        alpha[b * SDIM + s] = e;
        lsum += e;
    }
    red[tid] = lsum;
    __syncthreads();
    for (int o = 128; o > 0; o >>= 1) {
        if (tid < o) red[tid] += red[tid + o];
        __syncthreads();
    }
    float inv = 1.0f / red[0];
    __syncthreads();

    for (int s = tid; s < SDIM; s += 256)
        alpha[b * SDIM + s] *= inv;
}

// ---------------------------------------------------------------------------
// K4: cbar[b,i] = sum_s alpha[b,s] * context[b,s,i]
// ---------------------------------------------------------------------------
__global__ void k4_cbar(const float* __restrict__ context,
                        const float* __restrict__ alpha) {
    __shared__ float sal[128];
    int b  = blockIdx.y;
    int s0 = blockIdx.x * 128;
    int i  = threadIdx.x;
    if (i < 128) sal[i] = alpha[b * SDIM + s0 + i];
    __syncthreads();
    const float* cp = context + (size_t)b * SDIM * IDIM + (size_t)s0 * IDIM + i;
    float acc = 0.0f;
    #pragma unroll 4
    for (int s = 0; s < 128; s++) acc += sal[s] * cp[(size_t)s * IDIM];
    atomicAdd(&g_cbar[b * IDIM + i], acc);
}

// ---------------------------------------------------------------------------
// K5: hidden = Wc @ cbar + bc  (coalesced warp-per-row)
// ---------------------------------------------------------------------------
__global__ void __launch_bounds__(256) k5_out(const float* __restrict__ Wc,
                                              const float* __restrict__ bc,
                                              float* __restrict__ out) {
    __shared__ float sc[IDIM];
    int b  = blockIdx.x >> 2;
    int hq = blockIdx.x & 3;
    int tid = threadIdx.x;
    int wid = tid >> 5, lane = tid & 31;

    sc[tid] = g_cbar[b * IDIM + tid];
    sc[tid + 256] = g_cbar[b * IDIM + tid + 256];
    __syncthreads();

    const float4* s4 = (const float4*)sc;
    #pragma unroll 1
    for (int r = wid; r < 128; r += 8) {
        int h = hq * 128 + r;
        const float4* w4 = (const float4*)(Wc + (size_t)h * IDIM);
        float acc = 0.0f;
        #pragma unroll
        for (int j = 0; j < 4; j++) {
            float4 w = w4[lane + 32 * j];
            float4 s = s4[lane + 32 * j];
            acc += w.x * s.x + w.y * s.y + w.z * s.z + w.w * s.w;
        }
        #pragma unroll
        for (int o = 16; o > 0; o >>= 1) acc += __shfl_xor_sync(0xffffffffu, acc, o);
        if (lane == 0) out[b * HDIM + h] = acc + bc[h];
    }
}

// ---------------------------------------------------------------------------
extern "C" void kernel_launch(void* const* d_in, const int* in_sizes, int n_in,
                              void* d_out, int out_size) {
    const float* inp          = (const float*)d_in[0];
    const float* context      = (const float*)d_in[1];
    const unsigned char* mraw = (const unsigned char*)d_in[2];
    const float* Wl           = (const float*)d_in[3];
    const float* bl           = (const float*)d_in[4];
    const float* Wc           = (const float*)d_in[5];
    const float* bc           = (const float*)d_in[6];
    const float* Vv           = (const float*)d_in[7];

    float* out    = (float*)d_out;
    float* hidden = out;                   // [B, HID]
    float* alpha  = out + BDIM * HDIM;     // [B, S]

    cudaFuncSetAttribute(k2_att_mma, cudaFuncAttributeMaxDynamicSharedMemorySize, SMEM_K2);

    __nv_bfloat16 *ctx_hi, *wc_hi;
    unsigned char *ctx_h8, *ctx_l8, *wc_h8, *wc_l8;
    cudaGetSymbolAddress((void**)&ctx_hi, g_ctx_hi);
    cudaGetSymbolAddress((void**)&ctx_h8, g_ctx_h8);
    cudaGetSymbolAddress((void**)&ctx_l8, g_ctx_l8);
    cudaGetSymbolAddress((void**)&wc_hi, g_wc_hi);
    cudaGetSymbolAddress((void**)&wc_h8, g_wc_h8);
    cudaGetSymbolAddress((void**)&wc_l8, g_wc_l8);

    k0_detect<<<1, 256>>>(mraw);
    int n4c = BDIM * SDIM * IDIM / 4;
    k_conv<<<n4c / 256, 256>>>(context, ctx_hi, ctx_h8, ctx_l8, n4c);
    int n4w = HDIM * IDIM / 4;
    k_conv<<<n4w / 256, 256>>>(Wc, wc_hi, wc_h8, wc_l8, n4w);
    k1_hb<<<BDIM * 4, 256>>>(inp, Wl, bl, bc);
    k2_att_mma<<<BDIM * 16 * 4, 256, SMEM_K2>>>(Vv);
    k3_softmax<<<BDIM, 256>>>(mraw, alpha);
    k4_cbar<<<dim3(SDIM / 128, BDIM), 512>>>(context, alpha);
    k5_out<<<BDIM * 4, 256>>>(Wc, bc, hidden);
}

// round 9
// speedup vs baseline: 1.0392x; 1.0392x over previous
#include <cuda_runtime.h>
#include <cuda_bf16.h>
#include <math.h>
#include <stdint.h>

#define BDIM 64
#define SDIM 2048
#define IDIM 512
#define HDIM 512

// ---------------- device scratch (no cudaMalloc allowed) -------------------
__device__ float g_hb[BDIM * HDIM];
__device__ float g_att[BDIM * SDIM];
__device__ float g_cbar[BDIM * IDIM];
__device__ int   g_mask_is_byte;

__device__ __nv_bfloat16 g_wc_hi[HDIM * IDIM];
__device__ __nv_bfloat16 g_wc_lo[HDIM * IDIM];

// ---------------- PTX helpers (sm_80-level only) ----------------------------
__device__ __forceinline__ uint32_t smem_u32(const void* p) {
    uint32_t a;
    asm("{ .reg .u64 t; cvta.to.shared.u64 t, %1; cvt.u32.u64 %0, t; }" : "=r"(a) : "l"(p));
    return a;
}
#define CP16(dst, src) asm volatile("cp.async.cg.shared.global [%0], [%1], 16;" :: "r"(dst), "l"(src))
#define CP_COMMIT()    asm volatile("cp.async.commit_group;" ::: "memory")
#define CP_WAIT(n)     asm volatile("cp.async.wait_group %0;" :: "n"(n) : "memory")

#define LDSM4(r, a)                                                           \
    asm volatile("ldmatrix.sync.aligned.m8n8.x4.shared.b16 {%0,%1,%2,%3}, [%4];" \
        : "=r"((r)[0]), "=r"((r)[1]), "=r"((r)[2]), "=r"((r)[3]) : "r"(a))

#define MMA16816(c, a, b0, b1)                                                \
    asm volatile("mma.sync.aligned.m16n8k16.row.col.f32.bf16.bf16.f32 "       \
        "{%0,%1,%2,%3},{%4,%5,%6,%7},{%8,%9},{%0,%1,%2,%3};"                  \
        : "+f"((c)[0]), "+f"((c)[1]), "+f"((c)[2]), "+f"((c)[3])              \
        : "r"((a)[0]), "r"((a)[1]), "r"((a)[2]), "r"((a)[3]), "r"(b0), "r"(b1))

__device__ __forceinline__ uint32_t pack_bf16x2(float a, float b) {
    __nv_bfloat162 t(__float2bfloat16(a), __float2bfloat16(b));
    return *reinterpret_cast<uint32_t*>(&t);
}

// ---------------------------------------------------------------------------
// K0: detect mask storage (int32 vs uint8)
// ---------------------------------------------------------------------------
__global__ void k0_detect(const unsigned char* __restrict__ mraw) {
    __shared__ int found;
    if (threadIdx.x == 0) found = 0;
    __syncthreads();
    int acc = 0;
    for (int i = threadIdx.x; i < 4096; i += 256)
        if ((i & 3) != 0 && mraw[i] != 0) acc = 1;
    if (acc) atomicOr(&found, 1);
    __syncthreads();
    if (threadIdx.x == 0) g_mask_is_byte = found;
}

// ---------------------------------------------------------------------------
// Kc: fp32 -> (hi, lo) bf16 split (Wc only now; context converted inside k2)
// ---------------------------------------------------------------------------
__global__ void k_conv(const float* __restrict__ src, __nv_bfloat16* __restrict__ hi,
                       __nv_bfloat16* __restrict__ lo, int n4) {
    int i = blockIdx.x * blockDim.x + threadIdx.x;
    if (i >= n4) return;
    float4 v = ((const float4*)src)[i];
    __nv_bfloat16 h0 = __float2bfloat16(v.x), h1 = __float2bfloat16(v.y);
    __nv_bfloat16 h2 = __float2bfloat16(v.z), h3 = __float2bfloat16(v.w);
    __nv_bfloat16 l0 = __float2bfloat16(v.x - __bfloat162float(h0));
    __nv_bfloat16 l1 = __float2bfloat16(v.y - __bfloat162float(h1));
    __nv_bfloat16 l2 = __float2bfloat16(v.z - __bfloat162float(h2));
    __nv_bfloat16 l3 = __float2bfloat16(v.w - __bfloat162float(h3));
    __nv_bfloat162* hp = (__nv_bfloat162*)hi;
    __nv_bfloat162* lp = (__nv_bfloat162*)lo;
    hp[i * 2 + 0] = __nv_bfloat162(h0, h1);
    hp[i * 2 + 1] = __nv_bfloat162(h2, h3);
    lp[i * 2 + 0] = __nv_bfloat162(l0, l1);
    lp[i * 2 + 1] = __nv_bfloat162(l2, l3);
}

// ---------------------------------------------------------------------------
// K1: hb = inp@Wl.T + bl + bc ; zero g_cbar and g_att (warp-per-row, coalesced)
// ---------------------------------------------------------------------------
__global__ void __launch_bounds__(256) k1_hb(const float* __restrict__ inp,
                                             const float* __restrict__ Wl,
                                             const float* __restrict__ bl,
                                             const float* __restrict__ bc) {
    __shared__ float sin[IDIM];
    int b  = blockIdx.x >> 2;
    int hq = blockIdx.x & 3;
    int tid = threadIdx.x;
    int wid = tid >> 5, lane = tid & 31;

    sin[tid] = inp[b * IDIM + tid];
    sin[tid + 256] = inp[b * IDIM + tid + 256];
    g_att[b * SDIM + hq * 512 + tid * 2 + 0] = 0.0f;
    g_att[b * SDIM + hq * 512 + tid * 2 + 1] = 0.0f;
    if (tid < 128) g_cbar[b * IDIM + hq * 128 + tid] = 0.0f;
    __syncthreads();

    const float4* s4 = (const float4*)sin;
    #pragma unroll 1
    for (int r = wid; r < 128; r += 8) {
        int h = hq * 128 + r;
        const float4* w4 = (const float4*)(Wl + (size_t)h * IDIM);
        float acc = 0.0f;
        #pragma unroll
        for (int j = 0; j < 4; j++) {
            float4 w = w4[lane + 32 * j];
            float4 s = s4[lane + 32 * j];
            acc += w.x * s.x + w.y * s.y + w.z * s.z + w.w * s.w;
        }
        #pragma unroll
        for (int o = 16; o > 0; o >>= 1) acc += __shfl_xor_sync(0xffffffffu, acc, o);
        if (lane == 0) g_hb[b * HDIM + h] = acc + bl[h] + bc[h];
    }
}

// ---------------------------------------------------------------------------
// K2: bf16 hi/lo-split GEMM + tanh + V reduction, with IN-KERNEL fp32->bf16
// split of the context tile (LDG.128 -> cvt -> STS.128). No conv pass for ctx.
// CTA tile: 128(s) x 128(h), K=512 in 8 chunks of 64; 2-stage buffers.
// Stage (64KB): Ahi 16K | Alo 16K | Bhi 16K | Blo 16K
// grid = B * 16(stile) * 4(htile) = 4096 CTAs, 256 threads.
// ---------------------------------------------------------------------------
#define ST_AH 0u
#define ST_AL 16384u
#define ST_BH 32768u
#define ST_BL 49152u
#define STAGE_BYTES 65536u
#define SMEM_K2 (2 * STAGE_BYTES)

__global__ void __launch_bounds__(256, 1) k2_att_mma(const float* __restrict__ context,
                                                     const float* __restrict__ Vv) {
    extern __shared__ char smem[];
    __shared__ float sV[128], sHB[128], attred[128];
    uint32_t sb = smem_u32(smem);

    int tid  = threadIdx.x;
    int wid  = tid >> 5;
    int lane = tid & 31;
    int g    = lane >> 2;
    int tg   = lane & 3;
    int warp_m = wid & 1;
    int warp_n = wid >> 1;

    int bx = blockIdx.x;
    int b     = bx >> 6;
    int stile = (bx >> 2) & 15;
    int htile = bx & 3;
    int s0    = stile * 128;
    int hbase = htile * 128;
    int bb    = b * SDIM;

    if (tid < 128) {
        sV[tid]  = Vv[hbase + tid];
        sHB[tid] = g_hb[b * HDIM + hbase + tid];
        attred[tid] = 0.0f;
    }

    // A loader: thread -> (row, half-row of 32 fp32)
    int ar   = tid >> 1;
    int ahalf = tid & 1;
    const uint4* actx = (const uint4*)(context + (size_t)(bb + s0 + ar) * IDIM + ahalf * 32);

    uint4 regs[8];
    auto ldgA = [&](int kc) {
        const uint4* src = actx + kc * 16;   // 64 fp32 = 16 uint4 per row-chunk
        #pragma unroll
        for (int j = 0; j < 8; j++) regs[j] = src[j];
    };
    // convert regs -> bf16 hi/lo, store swizzled into stage
    auto stsA = [&](uint32_t stage_base) {
        #pragma unroll
        for (int q = 0; q < 4; q++) {
            uint4 ra = regs[q * 2], rb = regs[q * 2 + 1];
            float f0 = __uint_as_float(ra.x), f1 = __uint_as_float(ra.y);
            float f2 = __uint_as_float(ra.z), f3 = __uint_as_float(ra.w);
            float f4 = __uint_as_float(rb.x), f5 = __uint_as_float(rb.y);
            float f6 = __uint_as_float(rb.z), f7 = __uint_as_float(rb.w);
            uint4 hv, lv;
            hv.x = pack_bf16x2(f0, f1); hv.y = pack_bf16x2(f2, f3);
            hv.z = pack_bf16x2(f4, f5); hv.w = pack_bf16x2(f6, f7);
            float r0 = f0 - __bfloat162float(__float2bfloat16(f0));
            float r1 = f1 - __bfloat162float(__float2bfloat16(f1));
            float r2 = f2 - __bfloat162float(__float2bfloat16(f2));
            float r3 = f3 - __bfloat162float(__float2bfloat16(f3));
            float r4 = f4 - __bfloat162float(__float2bfloat16(f4));
            float r5 = f5 - __bfloat162float(__float2bfloat16(f5));
            float r6 = f6 - __bfloat162float(__float2bfloat16(f6));
            float r7 = f7 - __bfloat162float(__float2bfloat16(f7));
            lv.x = pack_bf16x2(r0, r1); lv.y = pack_bf16x2(r2, r3);
            lv.z = pack_bf16x2(r4, r5); lv.w = pack_bf16x2(r6, r7);
            uint32_t off = ((uint32_t)(ar * 128 + ahalf * 64 + q * 16))
                         ^ ((uint32_t)(ar & 7) << 4);
            *(uint4*)(smem + (stage_base - sb) + ST_AH + off) = hv;
            *(uint4*)(smem + (stage_base - sb) + ST_AL + off) = lv;
        }
    };
    // B loader via cp.async (preconverted Wc hi/lo)
    auto loadB = [&](int kc, uint32_t stage_base) {
        int k0 = kc * 64;
        #pragma unroll
        for (int j = 0; j < 8; j++) {
            int idx = j * 256 + tid;
            int sg  = idx >> 10;
            int rem = idx & 1023;
            int r = rem >> 3, c = rem & 7;
            const __nv_bfloat16* src = (sg ? g_wc_lo : g_wc_hi)
                + ((size_t)(hbase + r) * IDIM + k0 + c * 8);
            uint32_t o = (uint32_t)(r * 128 + c * 16);
            CP16(stage_base + ST_BH + (uint32_t)sg * 16384u
                 + (o ^ (uint32_t)((r & 7) << 4)), src);
        }
        CP_COMMIT();
    };

    // ldmatrix address components (128B rows, XOR swizzle)
    int arow  = warp_m * 64 + (lane & 15);
    uint32_t akoff = (uint32_t)(lane & 16);
    uint32_t axor  = (uint32_t)((lane & 7) << 4);
    int brow  = (lane & 7) + ((lane & 16) >> 1);
    uint32_t bkoff = (uint32_t)(((lane >> 3) & 1) * 16);

    uint32_t aoff[4], boff[2];
    #pragma unroll
    for (int t = 0; t < 4; t++) aoff[t] = (uint32_t)((arow + t * 16) * 128) + akoff;
    #pragma unroll
    for (int p = 0; p < 2; p++) boff[p] = (uint32_t)((warp_n * 32 + p * 16 + brow) * 128) + bkoff;

    float acc[4][4][4];
    #pragma unroll
    for (int t = 0; t < 4; t++)
        #pragma unroll
        for (int n = 0; n < 4; n++)
            #pragma unroll
            for (int c = 0; c < 4; c++) acc[t][n][c] = 0.0f;

    // ---- prologue: fill both stages
    uint32_t st0 = sb, st1 = sb + STAGE_BYTES;
    ldgA(0);
    loadB(0, st0);
    stsA(st0);
    ldgA(1);
    loadB(1, st1);
    stsA(st1);
    ldgA(2);            // consumed at iter 0
    CP_WAIT(1);         // B0 complete
    __syncthreads();

    #pragma unroll 1
    for (int i = 0; i < 8; i++) {
        uint32_t stb = (i & 1) ? st1 : st0;
        uint32_t AH = stb + ST_AH, AL = stb + ST_AL;
        uint32_t BH = stb + ST_BH, BL = stb + ST_BL;

        #pragma unroll
        for (int q = 0; q < 4; q++) {
            uint32_t qb = (uint32_t)(q * 32);
            uint32_t aH[4][4], aL[4][4], bH[2][4], bL[2][4];
            #pragma unroll
            for (int t = 0; t < 4; t++) {
                LDSM4(aH[t], AH + ((aoff[t] + qb) ^ axor));
                LDSM4(aL[t], AL + ((aoff[t] + qb) ^ axor));
            }
            #pragma unroll
            for (int p = 0; p < 2; p++) {
                LDSM4(bH[p], BH + ((boff[p] + qb) ^ axor));
                LDSM4(bL[p], BL + ((boff[p] + qb) ^ axor));
            }
            #pragma unroll
            for (int t = 0; t < 4; t++)
                #pragma unroll
                for (int nt = 0; nt < 4; nt++) {
                    int p  = nt >> 1;
                    int r0 = (nt & 1) * 2;
                    MMA16816(acc[t][nt], aH[t], bH[p][r0], bH[p][r0 + 1]);
                    MMA16816(acc[t][nt], aH[t], bL[p][r0], bL[p][r0 + 1]);
                    MMA16816(acc[t][nt], aL[t], bH[p][r0], bH[p][r0 + 1]);
                }
        }

        if (i + 2 < 8) {
            __syncthreads();          // everyone done reading stage i&1
            stsA(stb);                // chunk i+2 into stage (i+2)&1 == i&1
            loadB(i + 2, stb);
            if (i + 3 < 8) ldgA(i + 3);
            CP_WAIT(1);               // B_{i+1} complete
        } else {
            CP_WAIT(0);
        }
        __syncthreads();
    }

    // ---- epilogue: att[s] += sum_h V[h]*tanh(acc + hb[h])
    float rowsum[8];
    #pragma unroll
    for (int r = 0; r < 8; r++) rowsum[r] = 0.0f;
    #pragma unroll
    for (int t = 0; t < 4; t++) {
        #pragma unroll
        for (int nt = 0; nt < 4; nt++) {
            int hh = warp_n * 32 + nt * 8 + tg * 2;
            float v0 = sV[hh], v1 = sV[hh + 1];
            float h0 = sHB[hh], h1 = sHB[hh + 1];
            float* c = acc[t][nt];
            rowsum[t * 2 + 0] += v0 * tanhf(c[0] + h0) + v1 * tanhf(c[1] + h1);
            rowsum[t * 2 + 1] += v0 * tanhf(c[2] + h0) + v1 * tanhf(c[3] + h1);
        }
    }
    #pragma unroll
    for (int r = 0; r < 8; r++) {
        float s = rowsum[r];
        s += __shfl_xor_sync(0xffffffffu, s, 1);
        s += __shfl_xor_sync(0xffffffffu, s, 2);
        if (tg == 0) {
            int row = warp_m * 64 + (r >> 1) * 16 + (r & 1) * 8 + g;
            atomicAdd(&attred[row], s);
        }
    }
    __syncthreads();
    if (tid < 128) atomicAdd(&g_att[b * SDIM + s0 + tid], attred[tid]);
}

// ---------------------------------------------------------------------------
// K3: masked softmax over S per batch -> alpha
// ---------------------------------------------------------------------------
__device__ __forceinline__ bool mask_at(const unsigned char* m, int idx, int is_byte) {
    if (is_byte) return m[idx] != 0;
    return ((const int*)m)[idx] != 0;
}

__global__ void k3_softmax(const unsigned char* __restrict__ mraw,
                           float* __restrict__ alpha) {
    __shared__ float red[256];
    int b = blockIdx.x;
    int tid = threadIdx.x;
    int is_byte = g_mask_is_byte;
    const float NEG_INF = __int_as_float(0xff800000);

    float lmax = NEG_INF;
    for (int s = tid; s < SDIM; s += 256)
        if (!mask_at(mraw, b * SDIM + s, is_byte))
            lmax = fmaxf(lmax, g_att[b * SDIM + s]);
    red[tid] = lmax;
    __syncthreads();
    for (int o = 128; o > 0; o >>= 1) {
        if (tid < o) red[tid] = fmaxf(red[tid], red[tid + o]);
        __syncthreads();
    }
    float smax = red[0];
    __syncthreads();

    float lsum = 0.0f;
    for (int s = tid; s < SDIM; s += 256) {
        float e = 0.0f;
        if (!mask_at(mraw, b * SDIM + s, is_byte))
            e = expf(g_att[b * SDIM + s] - smax);
        alpha[b * SDIM + s] = e;
        lsum += e;
    }
    red[tid] = lsum;
    __syncthreads();
    for (int o = 128; o > 0; o >>= 1) {
        if (tid < o) red[tid] += red[tid + o];
        __syncthreads();
    }
    float inv = 1.0f / red[0];
    __syncthreads();

    for (int s = tid; s < SDIM; s += 256)
        alpha[b * SDIM + s] *= inv;
}

// ---------------------------------------------------------------------------
// K4: cbar[b,i] = sum_s alpha[b,s] * context[b,s,i]
// ---------------------------------------------------------------------------
__global__ void k4_cbar(const float* __restrict__ context,
                        const float* __restrict__ alpha) {
    __shared__ float sal[128];
    int b  = blockIdx.y;
    int s0 = blockIdx.x * 128;
    int i  = threadIdx.x;
    if (i < 128) sal[i] = alpha[b * SDIM + s0 + i];
    __syncthreads();
    const float* cp = context + (size_t)b * SDIM * IDIM + (size_t)s0 * IDIM + i;
    float acc = 0.0f;
    #pragma unroll 4
    for (int s = 0; s < 128; s++) acc += sal[s] * cp[(size_t)s * IDIM];
    atomicAdd(&g_cbar[b * IDIM + i], acc);
}

// ---------------------------------------------------------------------------
// K5: hidden = Wc @ cbar + bc  (coalesced warp-per-row)
// ---------------------------------------------------------------------------
__global__ void __launch_bounds__(256) k5_out(const float* __restrict__ Wc,
                                              const float* __restrict__ bc,
                                              float* __restrict__ out) {
    __shared__ float sc[IDIM];
    int b  = blockIdx.x >> 2;
    int hq = blockIdx.x & 3;
    int tid = threadIdx.x;
    int wid = tid >> 5, lane = tid & 31;

    sc[tid] = g_cbar[b * IDIM + tid];
    sc[tid + 256] = g_cbar[b * IDIM + tid + 256];
    __syncthreads();

    const float4* s4 = (const float4*)sc;
    #pragma unroll 1
    for (int r = wid; r < 128; r += 8) {
        int h = hq * 128 + r;
        const float4* w4 = (const float4*)(Wc + (size_t)h * IDIM);
        float acc = 0.0f;
        #pragma unroll
        for (int j = 0; j < 4; j++) {
            float4 w = w4[lane + 32 * j];
            float4 s = s4[lane + 32 * j];
            acc += w.x * s.x + w.y * s.y + w.z * s.z + w.w * s.w;
        }
        #pragma unroll
        for (int o = 16; o > 0; o >>= 1) acc += __shfl_xor_sync(0xffffffffu, acc, o);
        if (lane == 0) out[b * HDIM + h] = acc + bc[h];
    }
}

// ---------------------------------------------------------------------------
extern "C" void kernel_launch(void* const* d_in, const int* in_sizes, int n_in,
                              void* d_out, int out_size) {
    const float* inp          = (const float*)d_in[0];
    const float* context      = (const float*)d_in[1];
    const unsigned char* mraw = (const unsigned char*)d_in[2];
    const float* Wl           = (const float*)d_in[3];
    const float* bl           = (const float*)d_in[4];
    const float* Wc           = (const float*)d_in[5];
    const float* bc           = (const float*)d_in[6];
    const float* Vv           = (const float*)d_in[7];

    float* out    = (float*)d_out;
    float* hidden = out;                   // [B, HID]
    float* alpha  = out + BDIM * HDIM;     // [B, S]

    cudaFuncSetAttribute(k2_att_mma, cudaFuncAttributeMaxDynamicSharedMemorySize, SMEM_K2);

    __nv_bfloat16 *wc_hi, *wc_lo;
    cudaGetSymbolAddress((void**)&wc_hi, g_wc_hi);
    cudaGetSymbolAddress((void**)&wc_lo, g_wc_lo);

    k0_detect<<<1, 256>>>(mraw);
    int n4w = HDIM * IDIM / 4;
    k_conv<<<n4w / 256, 256>>>(Wc, wc_hi, wc_lo, n4w);
    k1_hb<<<BDIM * 4, 256>>>(inp, Wl, bl, bc);
    k2_att_mma<<<BDIM * 16 * 4, 256, SMEM_K2>>>(context, Vv);
    k3_softmax<<<BDIM, 256>>>(mraw, alpha);
    k4_cbar<<<dim3(SDIM / 128, BDIM), 512>>>(context, alpha);
    k5_out<<<BDIM * 4, 256>>>(Wc, bc, hidden);
}